// round 15
// baseline (speedup 1.0000x reference)
#include <cuda_runtime.h>
#include <cuda_bf16.h>
#include <math.h>
#include <stdint.h>

#define HDIM   256
#define BATCH  1024
#define TSTEPS 64
#define IMGD   2048
#define G4     1024
#define VOCAB  32000

// ---------------- device scratch (no allocation allowed) -------------------
__device__ float g_img[BATCH * HDIM];
__device__ float g_imgpart[4 * BATCH * HDIM];                // split-K partials
__device__ float g_proj[(size_t)VOCAB * G4];                 // vocab projection (131MB)
__device__ __nv_bfloat16 g_ehi[(size_t)VOCAB * HDIM];
__device__ __nv_bfloat16 g_elo[(size_t)VOCAB * HDIM];
__device__ __nv_bfloat16 g_ihi[(size_t)BATCH * IMGD];
__device__ __nv_bfloat16 g_ilo[(size_t)BATCH * IMGD];
__device__ __nv_bfloat16 g_wimgp[HDIM * 2 * IMGD];           // [n][0:2048]=hi,[2048:4096]=lo
__device__ __nv_bfloat16 g_wih[G4 * 2 * HDIM];               // [p][0:256]=hi, [256:512]=lo
__device__ __nv_bfloat16 g_whh[G4 * 2 * HDIM];
__device__ float g_biasp[G4];
__device__ __nv_bfloat16 g_hhi[2][BATCH * HDIM];
__device__ __nv_bfloat16 g_hlo[2][BATCH * HDIM];

// grid-barrier state (proven primitive)
__device__ int g_bar_count;
__device__ volatile unsigned g_bar_gen;

// ---------------- helpers ---------------------------------------------------
__device__ __forceinline__ uint32_t smem_u32(const void* p) {
    uint32_t a;
    asm("{ .reg .u64 t; cvta.to.shared.u64 t, %1; cvt.u32.u64 %0, t; }" : "=r"(a) : "l"(p));
    return a;
}
__device__ __forceinline__ void cp_async16(uint32_t saddr, const void* gaddr) {
    asm volatile("cp.async.cg.shared.global [%0], [%1], 16;" :: "r"(saddr), "l"(gaddr));
}
__device__ __forceinline__ void ldm_x4(uint32_t* r, uint32_t addr) {
    asm volatile("ldmatrix.sync.aligned.m8n8.x4.shared.b16 {%0,%1,%2,%3}, [%4];"
                 : "=r"(r[0]), "=r"(r[1]), "=r"(r[2]), "=r"(r[3]) : "r"(addr));
}
__device__ __forceinline__ void mma_bf16(float* d, const uint32_t* a, const uint32_t* b) {
    asm volatile("mma.sync.aligned.m16n8k16.row.col.f32.bf16.bf16.f32 "
                 "{%0,%1,%2,%3}, {%4,%5,%6,%7}, {%8,%9}, {%0,%1,%2,%3};"
                 : "+f"(d[0]), "+f"(d[1]), "+f"(d[2]), "+f"(d[3])
                 : "r"(a[0]), "r"(a[1]), "r"(a[2]), "r"(a[3]), "r"(b[0]), "r"(b[1]));
}

// proven grid barrier (R5/R7/R8/R12)
__device__ __forceinline__ void grid_barrier() {
    __threadfence();
    __syncthreads();
    if (threadIdx.x == 0) {
        unsigned gen = g_bar_gen;
        if (atomicAdd(&g_bar_count, 1) == (int)gridDim.x - 1) {
            g_bar_count = 0;
            __threadfence();
            g_bar_gen = gen + 1;
        } else {
            while (g_bar_gen == gen) __nanosleep(32);
        }
        __threadfence();
    }
    __syncthreads();
}

// ---------------- unified GEMM: proj tiles + img split-K tiles --------------
// bx <  64  : img tile  (m 8 x n 2 x z 4), 24 chunks, raw partials out
// bx >= 64  : proj tile (m 250 x n 8),     12 chunks, +biasp out
#define STG_BYTES 32768
#define XG_SMEM   (3 * STG_BYTES)
#define N_IMG_CTAS 64

__global__ __launch_bounds__(256)
void fused_gemm_kernel(float* __restrict__ Cproj, float* __restrict__ Cpart)
{
    extern __shared__ __align__(1024) char smem[];
    const uint32_t sbase = smem_u32(smem);
    const int t = threadIdx.x;
    const int lane = t & 31;
    const int wid = t >> 5;
    const int wm = wid >> 2;
    const int wn = wid & 3;

    const bool is_img = (blockIdx.x < N_IMG_CTAS);
    int m0, n0, zslice = 0;
    int nchunks, cshift, cmask, b_lo_off;
    const __nv_bfloat16 *a_hi, *a_lo, *b_row;

    const int lr = t >> 1;
    const int lhalf = t & 1;

    if (is_img) {
        const int j = blockIdx.x;
        m0 = (j & 7) * 128;
        n0 = ((j >> 3) & 1) * 128;
        zslice = j >> 4;                    // 0..3
        const int kb = zslice * 512;
        nchunks = 24; cshift = 3; cmask = 7; b_lo_off = IMGD;
        a_hi = g_ihi + (size_t)(m0 + lr) * IMGD + kb;
        a_lo = g_ilo + (size_t)(m0 + lr) * IMGD + kb;
        b_row = g_wimgp + (size_t)(n0 + lr) * (2 * IMGD) + kb;
    } else {
        const int j = blockIdx.x - N_IMG_CTAS;
        m0 = (j % 250) * 128;
        n0 = (j / 250) * 128;
        nchunks = 12; cshift = 2; cmask = 3; b_lo_off = HDIM;
        a_hi = g_ehi + (size_t)(m0 + lr) * HDIM;
        a_lo = g_elo + (size_t)(m0 + lr) * HDIM;
        b_row = g_wih + (size_t)(n0 + lr) * (2 * HDIM);
    }

    uint32_t sdst[4];
#pragma unroll
    for (int i = 0; i < 4; ++i) {
        const int w = lhalf * 4 + i;
        sdst[i] = (uint32_t)((lr * 8 + (w ^ (lr & 7))) * 16);
    }

    int rA[4], rB[4];
    const int mhi = lane >> 4;
    const int kq  = lane >> 3;
#pragma unroll
    for (int mf = 0; mf < 4; ++mf)
        rA[mf] = wm * 64 + mf * 16 + ((lane >> 3) & 1) * 8 + (lane & 7);
#pragma unroll
    for (int q = 0; q < 4; ++q)
        rB[q] = wn * 32 + q * 8 + (lane & 7);

    float acc[4][4][4];
#pragma unroll
    for (int i = 0; i < 4; ++i)
#pragma unroll
        for (int j = 0; j < 4; ++j)
#pragma unroll
            for (int r = 0; r < 4; ++r) acc[i][j][r] = 0.f;

    auto issue = [&](int c, int s) {
        const int term = c >> cshift;
        const int kcol = (c & cmask) * 64;
        const __nv_bfloat16* asrc = ((term == 1) ? a_lo : a_hi) + kcol;
        const __nv_bfloat16* bsrc = b_row + kcol + ((term == 2) ? b_lo_off : 0);
        const uint32_t sa = sbase + s * STG_BYTES;
        const uint32_t sb = sa + 16384;
#pragma unroll
        for (int i = 0; i < 4; ++i) {
            const int e = (lhalf * 4 + i) * 8;
            cp_async16(sa + sdst[i], asrc + e);
            cp_async16(sb + sdst[i], bsrc + e);
        }
        asm volatile("cp.async.commit_group;" ::: "memory");
    };

    issue(0, 0);
    issue(1, 1);

#pragma unroll 1
    for (int c = 0; c < nchunks; ++c) {
        if (c < nchunks - 1) asm volatile("cp.async.wait_group 1;" ::: "memory");
        else                 asm volatile("cp.async.wait_group 0;" ::: "memory");
        __syncthreads();
        if (c + 2 < nchunks) issue(c + 2, (c + 2) % 3);

        const uint32_t sa = sbase + (c % 3) * STG_BYTES;
        const uint32_t sb = sa + 16384;
#pragma unroll
        for (int ksp = 0; ksp < 2; ++ksp) {
            uint32_t bfr4[4][4];
#pragma unroll
            for (int q = 0; q < 4; ++q) {
                const int r = rB[q];
                ldm_x4(bfr4[q], sb + (uint32_t)((r * 8 + ((ksp * 4 + kq) ^ (r & 7))) * 16));
            }
#pragma unroll
            for (int ks2 = 0; ks2 < 2; ++ks2) {
                const int ks = ksp * 2 + ks2;
                uint32_t afr[4][4];
#pragma unroll
                for (int mf = 0; mf < 4; ++mf) {
                    const int r = rA[mf];
                    ldm_x4(afr[mf], sa + (uint32_t)((r * 8 + ((ks * 2 + mhi) ^ (r & 7))) * 16));
                }
#pragma unroll
                for (int mf = 0; mf < 4; ++mf)
#pragma unroll
                    for (int q = 0; q < 4; ++q)
                        mma_bf16(acc[mf][q], afr[mf], bfr4[q] + ks2 * 2);
            }
        }
    }

    const int mrow = m0 + wm * 64 + (lane >> 2);
    const int nco  = n0 + wn * 32 + (lane & 3) * 2;
    if (is_img) {
        float* cp = Cpart + (size_t)zslice * BATCH * HDIM;
#pragma unroll
        for (int q = 0; q < 4; ++q)
#pragma unroll
            for (int mf = 0; mf < 4; ++mf) {
                const int m = mrow + mf * 16;
                *(float2*)&cp[(size_t)m * HDIM + nco + q * 8] =
                    make_float2(acc[mf][q][0], acc[mf][q][1]);
                *(float2*)&cp[(size_t)(m + 8) * HDIM + nco + q * 8] =
                    make_float2(acc[mf][q][2], acc[mf][q][3]);
            }
    } else {
#pragma unroll
        for (int q = 0; q < 4; ++q) {
            const float bp0 = g_biasp[nco + q * 8];
            const float bp1 = g_biasp[nco + q * 8 + 1];
#pragma unroll
            for (int mf = 0; mf < 4; ++mf) {
                const int m = mrow + mf * 16;
                *(float2*)&Cproj[(size_t)m * G4 + nco + q * 8] =
                    make_float2(acc[mf][q][0] + bp0, acc[mf][q][1] + bp1);
                *(float2*)&Cproj[(size_t)(m + 8) * G4 + nco + q * 8] =
                    make_float2(acc[mf][q][2] + bp0, acc[mf][q][3] + bp1);
            }
        }
    }
}

__global__ void img_reduce_kernel(const float* __restrict__ bimg)
{
    const int i = blockIdx.x * 256 + threadIdx.x;
    const int n = i & (HDIM - 1);
    float s = g_imgpart[i] + g_imgpart[BATCH * HDIM + i]
            + g_imgpart[2 * BATCH * HDIM + i] + g_imgpart[3 * BATCH * HDIM + i];
    g_img[i] = fmaxf(s + bimg[n], 0.f);
}

// ---------------- persistent LSTM recurrence v8 -----------------------------
// R12 structure; A-load split hi/lo into two cp.async groups with the MMA
// reordered into pass1 (Ahi*Bhi + Ahi*Blo) / pass2 (Alo*Bhi) to hide latency.
#define PB_BYTES 131072
#define PA_BYTES 65536
#define PX_BYTES 33792
#define PS_SMEM  (PB_BYTES + PA_BYTES + PX_BYTES)

__global__ __launch_bounds__(512)
void lstm_persist_kernel(const int* __restrict__ cap, float* __restrict__ out)
{
    extern __shared__ __align__(1024) char smem[];
    const uint32_t sbB = smem_u32(smem);
    const uint32_t sbA = sbB + PB_BYTES;
    const uint32_t sbX = sbA + PA_BYTES;
    float* sx = (float*)(smem + PB_BYTES + PA_BYTES);

    const int t = threadIdx.x;
    const int lane = t & 31;
    const int wid = t >> 5;
    const int wm = wid >> 2;
    const int wn = wid & 3;
    const int mb = blockIdx.x & 15;
    const int nb = blockIdx.x >> 4;
    const int m0 = mb * 64;
    const int n0 = nb * 128;
    const int hcol = nb * 32;

#pragma unroll
    for (int i = 0; i < 16; ++i) {
        const int ug = i * 512 + t;
        const int r = ug >> 6, u = ug & 63;
        cp_async16(sbB + (uint32_t)((r * 64 + (u & ~7) + ((u & 7) ^ (r & 7))) * 16),
                   g_whh + (size_t)(n0 + r) * 512 + u * 8);
    }
    asm volatile("cp.async.commit_group;" ::: "memory");

    const int mhi = lane >> 4;
    const int kq  = lane >> 3;
    const int rA = wm * 16 + ((lane >> 3) & 1) * 8 + (lane & 7);
    int rB[4];
#pragma unroll
    for (int q = 0; q < 4; ++q)
        rB[q] = q * 32 + wn * 8 + (lane & 7);

    const int jl0 = wn * 8 + (lane & 3) * 2;

    float creg[2][2];
    float img_r[2][2];
#pragma unroll
    for (int h = 0; h < 2; ++h) {
        const int m = m0 + wm * 16 + (lane >> 2) + h * 8;
        creg[h][0] = 0.f; creg[h][1] = 0.f;
        img_r[h][0] = g_img[m * HDIM + hcol + jl0];
        img_r[h][1] = g_img[m * HDIM + hcol + jl0 + 1];
    }

    auto issueX = [&](int ts) {
        const int* capt = cap + ts * BATCH + m0;
#pragma unroll
        for (int i = 0; i < 4; ++i) {
            const int ug = i * 512 + t;
            const int r = ug >> 5, w = ug & 31;
            const int ci = __ldg(capt + r);
            cp_async16(sbX + (uint32_t)(r * 528 + w * 16),
                       g_proj + (size_t)ci * G4 + n0 + w * 4);
        }
        asm volatile("cp.async.commit_group;" ::: "memory");
    };

    // A half-loads: half=0 -> hi buffer, half=1 -> lo buffer (own group each)
    auto issueA = [&](const __nv_bfloat16* hsrc, int half) {
#pragma unroll
        for (int i = 0; i < 4; ++i) {
            const int idx = i * 512 + t;            // 0..2047
            const int r = idx >> 5, u = idx & 31;
            cp_async16(sbA + (uint32_t)(half * 32768 +
                           (r * 32 + (u & ~7) + ((u & 7) ^ (r & 7))) * 16),
                       hsrc + (size_t)(m0 + r) * HDIM + u * 8);
        }
        asm volatile("cp.async.commit_group;" ::: "memory");
    };

    issueX(0);

    asm volatile("cp.async.wait_group 1;" ::: "memory");
    __syncthreads();

#pragma unroll 1
    for (int ts = 0; ts < TSTEPS; ++ts) {
        const __nv_bfloat16* hhi_r = g_hhi[ts & 1];
        const __nv_bfloat16* hlo_r = g_hlo[ts & 1];
        __nv_bfloat16* hhi_w = g_hhi[(ts & 1) ^ 1];
        __nv_bfloat16* hlo_w = g_hlo[(ts & 1) ^ 1];
        float* out_t = out + (size_t)ts * BATCH * HDIM;

        if (ts) grid_barrier();

        issueA(hhi_r, 0);   // group: A-hi
        issueA(hlo_r, 1);   // group: A-lo
        asm volatile("cp.async.wait_group 1;" ::: "memory");  // X + A-hi done
        __syncthreads();

        float acc[4][4];
#pragma unroll
        for (int j = 0; j < 4; ++j)
#pragma unroll
            for (int r = 0; r < 4; ++r) acc[j][r] = 0.f;

        // ---- pass 1: Ahi*Bhi + Ahi*Blo (A-lo still in flight) ----
#pragma unroll 1
        for (int kc = 0; kc < 4; ++kc) {
#pragma unroll
            for (int ksp = 0; ksp < 2; ++ksp) {
                uint32_t bhi[4][4], blo[4][4];
#pragma unroll
                for (int q = 0; q < 4; ++q) {
                    const int r = rB[q];
                    const uint32_t sw = (uint32_t)(((ksp * 4 + kq) ^ (r & 7)) * 16);
                    ldm_x4(bhi[q], sbB + (uint32_t)((r * 64 + kc * 8) * 16) + sw);
                    ldm_x4(blo[q], sbB + (uint32_t)((r * 64 + 32 + kc * 8) * 16) + sw);
                }
#pragma unroll
                for (int ks2 = 0; ks2 < 2; ++ks2) {
                    const int ks = ksp * 2 + ks2;
                    uint32_t ahi[4];
                    const uint32_t aoff = (uint32_t)((rA * 32 + kc * 8 + ((ks * 2 + mhi) ^ (rA & 7))) * 16);
                    ldm_x4(ahi, sbA + aoff);
#pragma unroll
                    for (int q = 0; q < 4; ++q) {
                        mma_bf16(acc[q], ahi, bhi[q] + ks2 * 2);
                        mma_bf16(acc[q], ahi, blo[q] + ks2 * 2);
                    }
                }
            }
        }

        asm volatile("cp.async.wait_group 0;" ::: "memory");  // A-lo done
        __syncthreads();

        // ---- pass 2: Alo*Bhi ----
#pragma unroll 1
        for (int kc = 0; kc < 4; ++kc) {
#pragma unroll
            for (int ksp = 0; ksp < 2; ++ksp) {
                uint32_t bhi[4][4];
#pragma unroll
                for (int q = 0; q < 4; ++q) {
                    const int r = rB[q];
                    const uint32_t sw = (uint32_t)(((ksp * 4 + kq) ^ (r & 7)) * 16);
                    ldm_x4(bhi[q], sbB + (uint32_t)((r * 64 + kc * 8) * 16) + sw);
                }
#pragma unroll
                for (int ks2 = 0; ks2 < 2; ++ks2) {
                    const int ks = ksp * 2 + ks2;
                    uint32_t alo[4];
                    const uint32_t aoff = (uint32_t)(32768 + (rA * 32 + kc * 8 + ((ks * 2 + mhi) ^ (rA & 7))) * 16);
                    ldm_x4(alo, sbA + aoff);
#pragma unroll
                    for (int q = 0; q < 4; ++q)
                        mma_bf16(acc[q], alo, bhi[q] + ks2 * 2);
                }
            }
        }

        // ---- fused LSTM cell epilogue ----
#pragma unroll
        for (int h = 0; h < 2; ++h) {
            const int m = m0 + wm * 16 + (lane >> 2) + h * 8;
            const float* xr = sx + (m - m0) * 132;
            float hn[2];
#pragma unroll
            for (int jj = 0; jj < 2; ++jj) {
                const int jl = jl0 + jj;
                const int rs = h * 2 + jj;
                const float gi = acc[0][rs] + xr[jl];
                const float gf = acc[1][rs] + xr[32 + jl];
                const float gg = acc[2][rs] + xr[64 + jl];
                const float go = acc[3][rs] + xr[96 + jl];
                const float iv = 1.f / (1.f + expf(-gi));
                const float fv = 1.f / (1.f + expf(-gf));
                const float gv = tanhf(gg);
                const float ov = 1.f / (1.f + expf(-go));
                const float cn = fv * creg[h][jj] + iv * gv;
                hn[jj] = ov * tanhf(cn);
                creg[h][jj] = cn;
            }
            const int idx = m * HDIM + hcol + jl0;
            const __nv_bfloat16 h0 = __float2bfloat16(hn[0]);
            const __nv_bfloat16 h1 = __float2bfloat16(hn[1]);
            __nv_bfloat162 hhp; hhp.x = h0; hhp.y = h1;
            __nv_bfloat162 hlp;
            hlp.x = __float2bfloat16(hn[0] - __bfloat162float(h0));
            hlp.y = __float2bfloat16(hn[1] - __bfloat162float(h1));
            *(__nv_bfloat162*)&hhi_w[idx] = hhp;
            *(__nv_bfloat162*)&hlo_w[idx] = hlp;
            float2 ov2 = make_float2(hn[0] + img_r[h][0], hn[1] + img_r[h][1]);
            *(float2*)&out_t[idx] = ov2;
        }

        if (ts + 1 < TSTEPS) {
            __syncthreads();
            issueX(ts + 1);
        }
    }
}

// ---------------- prepacking: 4 elems per thread -----------------------------
#define S_EMB  ((size_t)VOCAB * HDIM)
#define S_W    ((size_t)G4 * HDIM)
#define S_HC   ((size_t)BATCH * HDIM)
#define S_IMG  ((size_t)BATCH * IMGD)
#define S_WIMG ((size_t)HDIM * IMGD)
#define PREP_TOTAL (S_EMB + 2 * S_W + S_HC + G4 + S_IMG + S_WIMG)
#define PREP_THREADS ((PREP_TOTAL + 3) / 4)

__device__ __forceinline__ void split4(const float* __restrict__ src,
                                       __nv_bfloat16* __restrict__ hi,
                                       __nv_bfloat16* __restrict__ lo, size_t i4)
{
    const float4 v = *(const float4*)(src + i4);
    __nv_bfloat162 h0, h1, l0, l1;
    h0.x = __float2bfloat16(v.x); h0.y = __float2bfloat16(v.y);
    h1.x = __float2bfloat16(v.z); h1.y = __float2bfloat16(v.w);
    l0.x = __float2bfloat16(v.x - __bfloat162float(h0.x));
    l0.y = __float2bfloat16(v.y - __bfloat162float(h0.y));
    l1.x = __float2bfloat16(v.z - __bfloat162float(h1.x));
    l1.y = __float2bfloat16(v.w - __bfloat162float(h1.y));
    *(__nv_bfloat162*)(hi + i4)     = h0;
    *(__nv_bfloat162*)(hi + i4 + 2) = h1;
    *(__nv_bfloat162*)(lo + i4)     = l0;
    *(__nv_bfloat162*)(lo + i4 + 2) = l1;
}

__global__ void prep_all_kernel(const float* __restrict__ emb,
                                const float* __restrict__ Wih,
                                const float* __restrict__ Whh,
                                const float* __restrict__ bih,
                                const float* __restrict__ bhh,
                                const float* __restrict__ img,
                                const float* __restrict__ Wimg)
{
    const size_t i = ((size_t)blockIdx.x * 256 + threadIdx.x) * 4;
    if (i < S_EMB) {
        split4(emb, g_ehi, g_elo, i);
    } else if (i < S_EMB + 2 * S_W) {
        const size_t ii = i - S_EMB;
        const int which = (int)(ii / S_W);
        const int idx = (int)(ii % S_W);
        const int p = idx >> 8, k = idx & 255;   // k..k+3 within row p
        const int nt = p >> 7, q = (p >> 5) & 3, j = p & 31;
        const int orig = q * 256 + nt * 32 + j;
        const float* W = which ? Whh : Wih;
        __nv_bfloat16* Wd = which ? g_whh : g_wih;
        const float4 v = *(const float4*)(W + orig * 256 + k);
        __nv_bfloat162 h0, h1, l0, l1;
        h0.x = __float2bfloat16(v.x); h0.y = __float2bfloat16(v.y);
        h1.x = __float2bfloat16(v.z); h1.y = __float2bfloat16(v.w);
        l0.x = __float2bfloat16(v.x - __bfloat162float(h0.x));
        l0.y = __float2bfloat16(v.y - __bfloat162float(h0.y));
        l1.x = __float2bfloat16(v.z - __bfloat162float(h1.x));
        l1.y = __float2bfloat16(v.w - __bfloat162float(h1.y));
        *(__nv_bfloat162*)(Wd + p * 512 + k)           = h0;
        *(__nv_bfloat162*)(Wd + p * 512 + k + 2)       = h1;
        *(__nv_bfloat162*)(Wd + p * 512 + 256 + k)     = l0;
        *(__nv_bfloat162*)(Wd + p * 512 + 256 + k + 2) = l1;
    } else if (i < S_EMB + 2 * S_W + S_HC) {
        const size_t idx = i - S_EMB - 2 * S_W;
        __nv_bfloat162 z; z.x = __float2bfloat16(0.f); z.y = z.x;
        *(__nv_bfloat162*)(&g_hhi[0][idx])     = z;
        *(__nv_bfloat162*)(&g_hhi[0][idx + 2]) = z;
        *(__nv_bfloat162*)(&g_hlo[0][idx])     = z;
        *(__nv_bfloat162*)(&g_hlo[0][idx + 2]) = z;
    } else if (i < S_EMB + 2 * S_W + S_HC + G4) {
        const int p0 = (int)(i - S_EMB - 2 * S_W - S_HC);
#pragma unroll
        for (int d = 0; d < 4; ++d) {
            const int p = p0 + d;
            const int nt = p >> 7, q = (p >> 5) & 3, j = p & 31;
            const int orig = q * 256 + nt * 32 + j;
            g_biasp[p] = bih[orig] + bhh[orig];
        }
    } else if (i < S_EMB + 2 * S_W + S_HC + G4 + S_IMG) {
        const size_t idx = i - (S_EMB + 2 * S_W + S_HC + G4);
        split4(img, g_ihi, g_ilo, idx);
    } else if (i < PREP_TOTAL) {
        const size_t idx = i - (S_EMB + 2 * S_W + S_HC + G4 + S_IMG);
        const int n = (int)(idx >> 11);
        const int k = (int)(idx & 2047);
        const float4 v = *(const float4*)(Wimg + idx);
        __nv_bfloat162 h0, h1, l0, l1;
        h0.x = __float2bfloat16(v.x); h0.y = __float2bfloat16(v.y);
        h1.x = __float2bfloat16(v.z); h1.y = __float2bfloat16(v.w);
        l0.x = __float2bfloat16(v.x - __bfloat162float(h0.x));
        l0.y = __float2bfloat16(v.y - __bfloat162float(h0.y));
        l1.x = __float2bfloat16(v.z - __bfloat162float(h1.x));
        l1.y = __float2bfloat16(v.w - __bfloat162float(h1.y));
        __nv_bfloat16* Wd = g_wimgp + (size_t)n * 4096;
        *(__nv_bfloat162*)(Wd + k)            = h0;
        *(__nv_bfloat162*)(Wd + k + 2)        = h1;
        *(__nv_bfloat162*)(Wd + 2048 + k)     = l0;
        *(__nv_bfloat162*)(Wd + 2048 + k + 2) = l1;
    }
}

// ---------------- launcher ---------------------------------------------------
extern "C" void kernel_launch(void* const* d_in, const int* in_sizes, int n_in,
                              void* d_out, int out_size)
{
    const float* img  = (const float*)d_in[0];
    const int*   cap  = (const int*)  d_in[1];
    const float* Wimg = (const float*)d_in[2];
    const float* bimg = (const float*)d_in[3];
    const float* emb  = (const float*)d_in[4];
    const float* Wih  = (const float*)d_in[5];
    const float* Whh  = (const float*)d_in[6];
    const float* bih  = (const float*)d_in[7];
    const float* bhh  = (const float*)d_in[8];
    float* out = (float*)d_out;

    float* p_proj;  cudaGetSymbolAddress((void**)&p_proj,  g_proj);
    float* p_ipart; cudaGetSymbolAddress((void**)&p_ipart, g_imgpart);

    cudaFuncSetAttribute(fused_gemm_kernel, cudaFuncAttributeMaxDynamicSharedMemorySize, XG_SMEM);
    cudaFuncSetAttribute(lstm_persist_kernel, cudaFuncAttributeMaxDynamicSharedMemorySize, PS_SMEM);

    prep_all_kernel<<<(int)((PREP_THREADS + 255) / 256), 256>>>(emb, Wih, Whh, bih, bhh, img, Wimg);

    // proj (2000 tiles) + img split-K (64 tiles) in one launch
    fused_gemm_kernel<<<2000 + N_IMG_CTAS, 256, XG_SMEM>>>(p_proj, p_ipart);

    img_reduce_kernel<<<(BATCH * HDIM) / 256, 256>>>(bimg);

    lstm_persist_kernel<<<128, 512, PS_SMEM>>>(cap, out);
}